// round 3
// baseline (speedup 1.0000x reference)
#include <cuda_runtime.h>
#include <cuda_bf16.h>
#include <cstdint>

#define DEVINL __device__ __forceinline__

// ---------------- problem dims ----------------
#define MTOK 16384   // B*S = 8*2048
#define DIN  4096
#define DOUT 4096

// ---------------- scratch (device globals; no allocs allowed) ----------------
__device__ int8_t g_xq[(size_t)MTOK * DIN];   // 64 MB quantized activations (int8)
__device__ int8_t g_wq[(size_t)DOUT * DIN];   // 16 MB ternary weights (int8)
__device__ float g_inv_scale[MTOK];           // per-token 1/(scale_x*scale_w)

// ---------------- PTX helpers (all valid on plain compute_103) ----------------
DEVINL uint32_t smem_u32(const void* p) {
    uint32_t a;
    asm("{ .reg .u64 t; cvta.to.shared.u64 t, %1; cvt.u32.u64 %0, t; }" : "=r"(a) : "l"(p));
    return a;
}
DEVINL void cp_async16(uint32_t dst, const void* src) {
    asm volatile("cp.async.cg.shared.global [%0], [%1], 16;" :: "r"(dst), "l"(src) : "memory");
}
DEVINL void cp_commit() { asm volatile("cp.async.commit_group;" ::: "memory"); }
template <int N>
DEVINL void cp_wait() { asm volatile("cp.async.wait_group %0;" :: "n"(N) : "memory"); }

DEVINL void ldsm_x4(uint32_t& r0, uint32_t& r1, uint32_t& r2, uint32_t& r3, uint32_t addr) {
    asm volatile("ldmatrix.sync.aligned.m8n8.x4.shared.b16 {%0,%1,%2,%3}, [%4];"
                 : "=r"(r0), "=r"(r1), "=r"(r2), "=r"(r3) : "r"(addr));
}
DEVINL void imma16832(int* d, const uint32_t* a, const uint32_t* b) {
    asm volatile(
        "mma.sync.aligned.m16n8k32.row.col.s32.s8.s8.s32 "
        "{%0,%1,%2,%3}, {%4,%5,%6,%7}, {%8,%9}, {%0,%1,%2,%3};"
        : "+r"(d[0]), "+r"(d[1]), "+r"(d[2]), "+r"(d[3])
        : "r"(a[0]), "r"(a[1]), "r"(a[2]), "r"(a[3]), "r"(b[0]), "r"(b[1]));
}

// ============================================================================
// Kernel 1: fused RMSNorm + per-token absmax quantization -> int8
// One block (256 threads) per token, 16 floats/thread.
// ============================================================================
__global__ __launch_bounds__(256) void quant_kernel(
    const float* __restrict__ x, const float* __restrict__ gamma,
    const float* __restrict__ scale_w)
{
    const int token = blockIdx.x;
    const int tid = threadIdx.x;
    const float4* xr = reinterpret_cast<const float4*>(x + (size_t)token * DIN);
    const float4* gr = reinterpret_cast<const float4*>(gamma);

    float4 v[4];
    float ss = 0.f;
#pragma unroll
    for (int i = 0; i < 4; ++i) {
        v[i] = xr[i * 256 + tid];
        ss += v[i].x * v[i].x + v[i].y * v[i].y + v[i].z * v[i].z + v[i].w * v[i].w;
    }
    __shared__ float red[8];
    __shared__ float redm[8];
#pragma unroll
    for (int o = 16; o; o >>= 1) ss += __shfl_xor_sync(~0u, ss, o);
    if ((tid & 31) == 0) red[tid >> 5] = ss;
    __syncthreads();
    float tot = 0.f;
#pragma unroll
    for (int i = 0; i < 8; ++i) tot += red[i];
    // rsqrt + one Newton step for full f32 accuracy
    const float varg = tot * (1.0f / DIN) + 1e-5f;
    float rstd = rsqrtf(varg);
    rstd = rstd * (1.5f - 0.5f * varg * rstd * rstd);

    float xn[16];
    float amax = 0.f;
#pragma unroll
    for (int i = 0; i < 4; ++i) {
        float4 g = gr[i * 256 + tid];
        xn[i * 4 + 0] = v[i].x * rstd * g.x;
        xn[i * 4 + 1] = v[i].y * rstd * g.y;
        xn[i * 4 + 2] = v[i].z * rstd * g.z;
        xn[i * 4 + 3] = v[i].w * rstd * g.w;
#pragma unroll
        for (int j = 0; j < 4; ++j) amax = fmaxf(amax, fabsf(xn[i * 4 + j]));
    }
#pragma unroll
    for (int o = 16; o; o >>= 1) amax = fmaxf(amax, fmaxf(__shfl_xor_sync(~0u, amax, o), amax));
    if ((tid & 31) == 0) redm[tid >> 5] = amax;
    __syncthreads();
    float am = 0.f;
#pragma unroll
    for (int i = 0; i < 8; ++i) am = fmaxf(am, redm[i]);
    const float sx = 127.0f / fmaxf(am, 1e-5f);

    uint32_t* oq = reinterpret_cast<uint32_t*>(g_xq + (size_t)token * DIN);
#pragma unroll
    for (int i = 0; i < 4; ++i) {
        int q[4];
#pragma unroll
        for (int j = 0; j < 4; ++j) {
            float r = rintf(xn[i * 4 + j] * sx);
            r = fminf(fmaxf(r, -128.f), 127.f);
            q[j] = (int)r;
        }
        uint32_t p = (uint32_t)(q[0] & 0xFF) | ((uint32_t)(q[1] & 0xFF) << 8) |
                     ((uint32_t)(q[2] & 0xFF) << 16) | ((uint32_t)(q[3] & 0xFF) << 24);
        oq[i * 256 + tid] = p;
    }
    if (tid == 0) g_inv_scale[token] = 1.0f / (sx * scale_w[0]);
}

// ============================================================================
// Kernel 2: ternary weight f32 {-1,0,1} -> int8
// ============================================================================
__global__ __launch_bounds__(256) void wconv_kernel(const float* __restrict__ w) {
    size_t i = (size_t)blockIdx.x * 256 + threadIdx.x;  // group of 4 elements
    float4 v = reinterpret_cast<const float4*>(w)[i];
    int q0 = (int)v.x, q1 = (int)v.y, q2 = (int)v.z, q3 = (int)v.w;
    uint32_t p = (uint32_t)(q0 & 0xFF) | ((uint32_t)(q1 & 0xFF) << 8) |
                 ((uint32_t)(q2 & 0xFF) << 16) | ((uint32_t)(q3 & 0xFF) << 24);
    reinterpret_cast<uint32_t*>(g_wq)[i] = p;
}

// ============================================================================
// Kernel 3: int8 IMMA GEMM  out[m,n] = (xq . w^T)[m,n] * inv_scale[m] + bias[n]
// BM=128, BN=128, BK=128 bytes, 3-stage cp.async, ldmatrix + m16n8k32 s8.
// 8 warps: warp_m in {0,1} (64 rows), warp_n in {0..3} (32 cols).
// ============================================================================
#define BM 128
#define BN 128
#define BK 128
#define STAGES 3
#define ITERS (DIN / BK)                 // 32
#define TILE_BYTES (BM * BK)             // 16 KB
#define STAGE_BYTES (2 * TILE_BYTES)     // 32 KB (A + B)
#define SMEM_DYN_TOTAL (STAGES * STAGE_BYTES)  // 96 KB

__global__ __launch_bounds__(256, 2)
void gemm_kernel(const float* __restrict__ bias, float* __restrict__ out)
{
    extern __shared__ __align__(1024) char smem[];
    const uint32_t sbase = smem_u32(smem);
    const int tid = threadIdx.x;
    const int wid = tid >> 5, lane = tid & 31;
    const int warp_m = wid >> 2;        // 0..1  (64 rows each)
    const int warp_n = wid & 3;         // 0..3  (32 cols each)
    const int tile_n = blockIdx.x;      // 0..31
    const int tile_m = blockIdx.y;      // 0..127

    const int8_t* Ag = g_xq + (size_t)tile_m * BM * DIN;
    const int8_t* Bg = g_wq + (size_t)tile_n * BN * DIN;

    // ---- producer: load k-chunk `it` into stage s ----
    auto load_stage = [&](int it, int s) {
        const uint32_t sa = sbase + s * STAGE_BYTES;
        const uint32_t sb = sa + TILE_BYTES;
        const int8_t* ap = Ag + (size_t)it * BK;
        const int8_t* bp = Bg + (size_t)it * BK;
#pragma unroll
        for (int i = 0; i < 4; ++i) {   // A: 1024 x 16B chunks / 256 threads
            int c = tid + i * 256;
            int r = c >> 3, j = c & 7;
            uint32_t off = (uint32_t)(r * 128) + (uint32_t)((j * 16) ^ ((r & 7) << 4));
            cp_async16(sa + off, ap + (size_t)r * DIN + j * 16);
        }
#pragma unroll
        for (int i = 0; i < 4; ++i) {   // B: same shape
            int c = tid + i * 256;
            int r = c >> 3, j = c & 7;
            uint32_t off = (uint32_t)(r * 128) + (uint32_t)((j * 16) ^ ((r & 7) << 4));
            cp_async16(sb + off, bp + (size_t)r * DIN + j * 16);
        }
    };

    // ---- per-lane ldmatrix address components ----
    // A (m16k32 tile): matrices 0..3 = [rows0-7,k0-15][rows8-15,k0-15][rows0-7,k16-31][rows8-15,k16-31]
    const int am = lane >> 3, ar = lane & 7;
    const uint32_t a_rowoff = (uint32_t)((warp_m * 64 + ((am & 1) << 3) + ar) * 128);
    const uint32_t a_bbase = (uint32_t)((am >> 1) * 16);
    const uint32_t a_xor = (uint32_t)(ar << 4);
    // B (two n8k32 tiles per x4): matrices 0..3 = [n0-7,k0-15][n0-7,k16-31][n8-15,k0-15][n8-15,k16-31]
    const uint32_t b_rowoff = (uint32_t)((warp_n * 32 + ((am >> 1) * 8) + ar) * 128);
    const uint32_t b_bbase = (uint32_t)((am & 1) * 16);
    const uint32_t b_xor = (uint32_t)(ar << 4);

    int acc[2][4][4];  // NOTE: warp tile is 64x32 => 4 m-tiles x 4 n-tiles
    int accv[4][4][4];
#pragma unroll
    for (int mt = 0; mt < 4; ++mt)
#pragma unroll
        for (int nt = 0; nt < 4; ++nt)
#pragma unroll
            for (int q = 0; q < 4; ++q) accv[mt][nt][q] = 0;
    (void)acc;

    // ---- prologue: stages 0,1 ----
    load_stage(0, 0); cp_commit();
    load_stage(1, 1); cp_commit();

    for (int it = 0; it < ITERS; ++it) {
        cp_wait<1>();
        __syncthreads();
        // issue next stage (always commit to keep group numbering)
        if (it + 2 < ITERS) load_stage(it + 2, (it + 2) % STAGES);
        cp_commit();

        const uint32_t sa = sbase + (it % STAGES) * STAGE_BYTES;
        const uint32_t sb = sa + TILE_BYTES;
#pragma unroll
        for (int ks = 0; ks < 4; ++ks) {      // 4 x k32 per 128B tile
            uint32_t a[4][4];
#pragma unroll
            for (int mt = 0; mt < 4; ++mt) {
                uint32_t addr = sa + a_rowoff + mt * (16 * 128) +
                                (((uint32_t)(ks * 32) + a_bbase) ^ a_xor);
                ldsm_x4(a[mt][0], a[mt][1], a[mt][2], a[mt][3], addr);
            }
            uint32_t b[4][2];
#pragma unroll
            for (int j = 0; j < 2; ++j) {     // each x4 covers n-tiles 2j, 2j+1
                uint32_t addr = sb + b_rowoff + j * (16 * 128) +
                                (((uint32_t)(ks * 32) + b_bbase) ^ b_xor);
                ldsm_x4(b[2 * j][0], b[2 * j][1], b[2 * j + 1][0], b[2 * j + 1][1], addr);
            }
#pragma unroll
            for (int mt = 0; mt < 4; ++mt)
#pragma unroll
                for (int nt = 0; nt < 4; ++nt)
                    imma16832(accv[mt][nt], a[mt], b[nt]);
        }
    }

    // ---- epilogue: s32 -> f32 * inv_scale[m] + bias[n] ----
    const int row0 = tile_m * BM + warp_m * 64 + (lane >> 2);
    const int col0 = tile_n * BN + warp_n * 32 + (lane & 3) * 2;
#pragma unroll
    for (int mt = 0; mt < 4; ++mt) {
        const int rlo = row0 + mt * 16;
        const float inv_lo = g_inv_scale[rlo];
        const float inv_hi = g_inv_scale[rlo + 8];
#pragma unroll
        for (int nt = 0; nt < 4; ++nt) {
            const int c = col0 + nt * 8;
            const float b0 = __ldg(bias + c);
            const float b1 = __ldg(bias + c + 1);
            float2 lo, hi;
            lo.x = (float)accv[mt][nt][0] * inv_lo + b0;
            lo.y = (float)accv[mt][nt][1] * inv_lo + b1;
            hi.x = (float)accv[mt][nt][2] * inv_hi + b0;
            hi.y = (float)accv[mt][nt][3] * inv_hi + b1;
            *reinterpret_cast<float2*>(out + (size_t)rlo * DOUT + c) = lo;
            *reinterpret_cast<float2*>(out + (size_t)(rlo + 8) * DOUT + c) = hi;
        }
    }
}

// ============================================================================
// launch
// ============================================================================
extern "C" void kernel_launch(void* const* d_in, const int* in_sizes, int n_in,
                              void* d_out, int out_size) {
    (void)in_sizes; (void)n_in; (void)out_size;
    const float* x       = (const float*)d_in[0];
    const float* w       = (const float*)d_in[1];
    const float* scale_w = (const float*)d_in[2];
    const float* gamma   = (const float*)d_in[3];
    const float* bias    = (const float*)d_in[4];
    float* out = (float*)d_out;

    cudaFuncSetAttribute(gemm_kernel, cudaFuncAttributeMaxDynamicSharedMemorySize, SMEM_DYN_TOTAL);

    quant_kernel<<<MTOK, 256>>>(x, gamma, scale_w);
    wconv_kernel<<<(int)((size_t)DOUT * DIN / 4 / 256), 256>>>(w);
    gemm_kernel<<<dim3(DOUT / BN, MTOK / BM), 256, SMEM_DYN_TOTAL>>>(bias, out);
}